// round 3
// baseline (speedup 1.0000x reference)
#include <cuda_runtime.h>
#include <cstdint>

// BFP quantize/dequantize: blocks of 16 contiguous fp32 share exponent
// e = floor(log2(max|x|)); q = clip(rint(x * 2^(7-e)), -128, 127); out = q * 2^(e-7).
//
// Layout: 1 float4 per thread per iteration; 4 consecutive lanes form one
// 16-elem BFP block -> each warp LDG.128 covers a contiguous 512 B.
// Block max via 2 butterfly shuffles within the 4-lane group.
// 2 independent float4s in flight per thread (MLP_p1 = 2).

__device__ __forceinline__ float4 bfp_qdq_vec(float4 v)
{
    // local max|.| over this thread's 4 elements
    float m = fmaxf(fmaxf(fabsf(v.x), fabsf(v.y)),
                    fmaxf(fabsf(v.z), fabsf(v.w)));
    // reduce across the 4-lane group (lanes l^1, l^2 hold the same BFP block)
    m = fmaxf(m, __shfl_xor_sync(0xFFFFFFFFu, m, 1));
    m = fmaxf(m, __shfl_xor_sync(0xFFFFFFFFu, m, 2));

    float4 o;
    if (m > 0.0f) {
        // biased exponent of block max; floor(log2(m)) = eb - 127 for normals
        unsigned eb = __float_as_uint(m) >> 23;
        eb = eb < 8u ? 8u : eb;   // keep bit-built scales finite (denormal max)
        float scale = __uint_as_float((eb - 7u) << 23);   // 2^(e-7)
        float inv   = __uint_as_float((261u - eb) << 23); // 2^(7-e)

        o.x = fminf(127.0f, fmaxf(-128.0f, rintf(v.x * inv))) * scale;
        o.y = fminf(127.0f, fmaxf(-128.0f, rintf(v.y * inv))) * scale;
        o.z = fminf(127.0f, fmaxf(-128.0f, rintf(v.z * inv))) * scale;
        o.w = fminf(127.0f, fmaxf(-128.0f, rintf(v.w * inv))) * scale;
    } else {
        o.x = 0.0f; o.y = 0.0f; o.z = 0.0f; o.w = 0.0f;
    }
    return o;
}

__global__ void __launch_bounds__(256) bfp_qdq_kernel(
    const float4* __restrict__ in, float4* __restrict__ out, int n4)
{
    int stride = gridDim.x * blockDim.x;
    int i0 = blockIdx.x * blockDim.x + threadIdx.x;
    int i1 = i0 + stride;

    if (i1 < n4) {
        // fast path: both loads issued back-to-back (MLP=2)
        float4 v0 = in[i0];
        float4 v1 = in[i1];
        float4 o0 = bfp_qdq_vec(v0);
        float4 o1 = bfp_qdq_vec(v1);
        out[i0] = o0;
        out[i1] = o1;
    } else if (i0 < n4) {
        out[i0] = bfp_qdq_vec(in[i0]);
    }
}

extern "C" void kernel_launch(void* const* d_in, const int* in_sizes, int n_in,
                              void* d_out, int out_size)
{
    const float4* in  = (const float4*)d_in[0];
    float4*       out = (float4*)d_out;
    int n  = in_sizes[0];          // 134,217,728 (divisible by 16)
    int n4 = n >> 2;               // float4 count = 33,554,432

    const int threads = 256;
    const int per_cta = threads * 2;               // 2 float4s per thread
    int blocks = (n4 + per_cta - 1) / per_cta;     // 65,536 CTAs
    bfp_qdq_kernel<<<blocks, threads>>>(in, out, n4);
}